// round 3
// baseline (speedup 1.0000x reference)
#include <cuda_runtime.h>

// Random_RNN two-hop sparse propagation — single-pass bucket build, ILP-tuned.
//
// Hop1: acc1[j][b] = sum_{in-edges dst=j} w * x[b][src]
// Hop2: out[b][o]  = sum_{ass-edges dst=OUT0+o} w * acc1[src][b]
// Only ass-edges landing on OUTPUT nodes matter (~52K of ~891K) -> filter.
//
// All phases are LATENCY-bound (tiny working set, scattered), so: explicit
// independent loads per thread (MLP>=4) in the big a_dst scan, and few fat
// blocks in the hop gathers. Buckets have >8-sigma degree headroom; counters
// are consumed-and-reset by the hop kernels so graph replays are deterministic.

#define B      128
#define IN_F   256
#define N_ASS  4096
#define OUT_F  256
#define ASS0   256
#define OUT0   (IN_F + N_ASS)   // 4352
#define CAP1   96               // assoc in-degree: E 12.8, sd 3.5
#define CAP2   448              // output in-degree: E 204.8, sd 14

__device__ float2 g_b1[N_ASS * CAP1];   // {src*B (int bits), w}
__device__ float2 g_b2[OUT_F * CAP2];
__device__ int    g_c1[N_ASS];          // zero at every launch entry
__device__ int    g_c2[OUT_F];
__device__ float  g_xT[IN_F * B];
__device__ float  g_acc1[N_ASS * B];

// ---------------------------------------------------------------- build
// Grid sized so each thread owns UNROLL=4 independent int4 dst-loads.
__global__ void k_build(const float* __restrict__ x,
                        const int* __restrict__ in_src, const int* __restrict__ in_dst,
                        const float* __restrict__ in_w, int E_in,
                        const int* __restrict__ a_src, const int* __restrict__ a_dst,
                        const float* __restrict__ a_w, int E_ass) {
    int i  = blockIdx.x * blockDim.x + threadIdx.x;
    int nt = gridDim.x * blockDim.x;

    // x [B][IN_F] -> xT [IN_F][B]
    for (int idx = i; idx < IN_F * B; idx += nt) {
        int b = idx >> 8, s = idx & 255;
        g_xT[s * B + b] = x[idx];
    }

    // hop1 edges (~52K)
    for (int e = i; e < E_in; e += nt) {
        int d   = in_dst[e] - ASS0;
        int pos = atomicAdd(&g_c1[d], 1);
        g_b1[d * CAP1 + pos] = make_float2(__int_as_float(in_src[e] * B), in_w[e]);
    }

    // hop2 edges (~891K): 4 independent int4 loads per thread, then filter
    int E4 = E_ass >> 2;
    const int4* a4 = (const int4*)a_dst;
    for (int q0 = i; q0 < E4; q0 += 4 * nt) {
        int4 d4[4]; int qq[4]; bool v[4];
#pragma unroll
        for (int k = 0; k < 4; k++) {
            qq[k] = q0 + k * nt;
            v[k]  = qq[k] < E4;
            d4[k] = v[k] ? __ldg(&a4[qq[k]]) : make_int4(0, 0, 0, 0);
        }
#pragma unroll
        for (int k = 0; k < 4; k++) {
            if (!v[k]) continue;
            int e = qq[k] << 2;
            int dd[4] = {d4[k].x, d4[k].y, d4[k].z, d4[k].w};
#pragma unroll
            for (int m = 0; m < 4; m++) {
                if (dd[m] >= OUT0) {
                    int d   = dd[m] - OUT0;
                    int s   = a_src[e + m] - ASS0;   // independent of the atomic
                    float w = a_w[e + m];
                    int pos = atomicAdd(&g_c2[d], 1);
                    g_b2[d * CAP2 + pos] = make_float2(__int_as_float(s * B), w);
                }
            }
        }
    }
    // tail (E_ass % 4)
    for (int e = (E4 << 2) + i; e < E_ass; e += nt) {
        int d = a_dst[e];
        if (d >= OUT0) {
            int dd  = d - OUT0;
            int s   = a_src[e] - ASS0;
            float w = a_w[e];
            int pos = atomicAdd(&g_c2[dd], 1);
            g_b2[dd * CAP2 + pos] = make_float2(__int_as_float(s * B), w);
        }
    }
}

// ---------------------------------------------------------------- hop 1
// 4 nodes per 512-thread block; 128 threads (one per batch elem) per node.
__global__ __launch_bounds__(512) void k_hop1() {
    __shared__ int sn[4];
    int g = threadIdx.x >> 7;              // node group 0..3
    int b = threadIdx.x & 127;
    int j = (blockIdx.x << 2) + g;
    if (b == 0) { sn[g] = g_c1[j]; g_c1[j] = 0; }
    __syncthreads();
    int n = sn[g];
    const float2* bk = &g_b1[j * CAP1];
    float r = 0.f;
    int e = 0;
    for (; e + 4 <= n; e += 4) {
        float2 p0 = bk[e], p1 = bk[e + 1], p2 = bk[e + 2], p3 = bk[e + 3];
        r += p0.y * g_xT[__float_as_int(p0.x) + b];
        r += p1.y * g_xT[__float_as_int(p1.x) + b];
        r += p2.y * g_xT[__float_as_int(p2.x) + b];
        r += p3.y * g_xT[__float_as_int(p3.x) + b];
    }
    for (; e < n; e++) { float2 p = bk[e]; r += p.y * g_xT[__float_as_int(p.x) + b]; }
    g_acc1[j * B + b] = r;
}

// ---------------------------------------------------------------- hop 2
// 4 output nodes per 512-thread block; 8-wide gather unroll.
__global__ __launch_bounds__(512) void k_hop2(float* __restrict__ out) {
    __shared__ int sn[4];
    int g = threadIdx.x >> 7;
    int b = threadIdx.x & 127;
    int o = (blockIdx.x << 2) + g;
    if (b == 0) { sn[g] = g_c2[o]; g_c2[o] = 0; }
    __syncthreads();
    int n = sn[g];
    const float2* bk = &g_b2[o * CAP2];
    float r = 0.f;
    int e = 0;
    for (; e + 8 <= n; e += 8) {
        float2 p[8];
#pragma unroll
        for (int k = 0; k < 8; k++) p[k] = bk[e + k];
#pragma unroll
        for (int k = 0; k < 8; k++) r += p[k].y * g_acc1[__float_as_int(p[k].x) + b];
    }
    for (; e < n; e++) { float2 p = bk[e]; r += p.y * g_acc1[__float_as_int(p.x) + b]; }
    out[b * OUT_F + o] = r;
}

// ---------------------------------------------------------------- launch
extern "C" void kernel_launch(void* const* d_in, const int* in_sizes, int n_in,
                              void* d_out, int out_size) {
    const float* x      = (const float*)d_in[0];
    const float* in_w   = (const float*)d_in[1];
    const float* a_w    = (const float*)d_in[2];
    const int*   in_src = (const int*)d_in[3];
    const int*   in_dst = (const int*)d_in[4];
    const int*   a_src  = (const int*)d_in[5];
    const int*   a_dst  = (const int*)d_in[6];
    int E_in  = in_sizes[1];
    int E_ass = in_sizes[2];
    float* out = (float*)d_out;

    // grid so each thread owns ~4 int4 loads in the big scan
    int E4      = E_ass >> 2;
    int threads = (E4 + 3) >> 2;
    int blocks  = (threads + 255) >> 8;
    if (blocks < 148) blocks = 148;

    k_build<<<blocks, 256>>>(x, in_src, in_dst, in_w, E_in, a_src, a_dst, a_w, E_ass);
    k_hop1 <<<N_ASS / 4, 512>>>();
    k_hop2 <<<OUT_F / 4, 512>>>(out);
}